// round 12
// baseline (speedup 1.0000x reference)
#include <cuda_runtime.h>
#include <cuda_fp16.h>
#include <cstdint>

// Shapes fixed by setup_inputs():
//   grid:     (N=2, C=12, D=8, Hg=16, Wg=16) float32
//   guidemap: (N=2, 1, H=1024, W=1024)       float32
//   out:      (N=2, C=12, H=1024, W=1024)    float32
#define HW   (1024 * 1024)
#define Cc   12
#define Dd   8
#define HG   16
#define WG   16

// Per-row table entry s = (c*15 + x0)*7 + z0, uint2 = 4 x fp16:
//   .x = half2( Gy(z0,x0),   Gy(z0+1,x0)   )
//   .y = half2( Gy(z0,x0+1), Gy(z0+1,x0+1) )
// Gy = grid y-lerped at that row. One LDS.64 per channel gives all 4 corners.
#define NTAB (Cc * 15 * 7)                 // 1260 entries, 10,080 B per row
__device__ uint2 g_tab[2 * 1024 * NTAB];   // 20.6 MB static scratch (both n)

// ---------------- packed fp32x2 helpers (FFMA2 in SASS, PTX-only) ----------
static __device__ __forceinline__ uint64_t fma_f32x2(uint64_t a, uint64_t b, uint64_t c) {
    uint64_t d; asm("fma.rn.f32x2 %0, %1, %2, %3;" : "=l"(d) : "l"(a), "l"(b), "l"(c)); return d;
}
static __device__ __forceinline__ uint64_t mul_f32x2(uint64_t a, uint64_t b) {
    uint64_t d; asm("mul.rn.f32x2 %0, %1, %2;" : "=l"(d) : "l"(a), "l"(b)); return d;
}
static __device__ __forceinline__ uint64_t pack2(float lo, float hi) {
    uint64_t d; asm("mov.b64 %0, {%1, %2};" : "=l"(d) : "f"(lo), "f"(hi)); return d;
}
static __device__ __forceinline__ float sum2(uint64_t v) {
    float lo, hi; asm("mov.b64 {%0, %1}, %2;" : "=f"(lo), "=f"(hi) : "l"(v)); return lo + hi;
}

// ================= Pre-kernel: build all row tables ========================
// Master staged in SMEM with z PADDED to stride 9 (z-fastest, 1 bank apart):
//   mp[(c*256 + y*16 + x)*9 + z]  -> z-varying gathers are conflict-free.
#define MP_FLOATS (Cc * 256 * 9)           // 27648 floats = 110,592 B
#define PRE_TPB 1024
#define PRE_BX  74

__global__ __launch_bounds__(PRE_TPB, 1)
void build_tables_kernel(const float* __restrict__ grid)
{
    extern __shared__ float mp[];
    const int n   = blockIdx.y;
    const int tid = threadIdx.x;

    // Stage grid[n] into padded master. src s = (c*8+z)*256 + pt (x fastest).
    const float* gsrc = grid + (size_t)n * (Cc * Dd * 256);
    for (int s = tid; s < Cc * Dd * 256; s += PRE_TPB) {
        int c   = s >> 11;
        int rem = s & 2047;
        int z   = rem >> 8;
        int pt  = rem & 255;
        mp[(c * 256 + pt) * 9 + z] = __ldg(gsrc + s);
    }
    __syncthreads();

    const float sxy = 15.0f / 1023.0f;
    uint2* gt = g_tab + (size_t)n * 1024 * NTAB;

    for (int y = blockIdx.x; y < 1024; y += PRE_BX) {
        const float fy  = (float)y * sxy;
        const int   iy0 = min((int)fy, HG - 2);
        const float wy  = fy - (float)iy0;
        uint2* gtr = gt + y * NTAB;

        for (int s = tid; s < NTAB; s += PRE_TPB) {
            int c  = s / 105;
            int r  = s - c * 105;
            int x0 = r / 7;
            int z0 = r - x0 * 7;
            const float* m = mp + (c * 256 + iy0 * 16 + x0) * 9 + z0;
            // offsets within mp: z+1 -> +1, x+1 -> +9, y+1 -> +144
            float a00 = m[0]   + wy * (m[144] - m[0]);     // z0 , x0
            float a10 = m[1]   + wy * (m[145] - m[1]);     // z1 , x0
            float a01 = m[9]   + wy * (m[153] - m[9]);     // z0 , x1
            float a11 = m[10]  + wy * (m[154] - m[10]);    // z1 , x1
            __half2 h0 = __floats2half2_rn(a00, a10);
            __half2 h1 = __floats2half2_rn(a01, a11);
            uint2 q;
            q.x = *reinterpret_cast<const unsigned int*>(&h0);
            q.y = *reinterpret_cast<const unsigned int*>(&h1);
            gtr[s] = q;
        }
    }
}

// ================= Main kernel: slice using precomputed tables =============
#define TPB 512          // each thread: columns tid and tid+512
#define BX  148          // 148 * 2 batches = 296 blocks = 2 per SM (occ ~100%)

__global__ __launch_bounds__(TPB, 2)
void slice_operation_kernel(const float* __restrict__ guide,
                            float* __restrict__ out)
{
    __shared__ uint2 tabs[2 * NTAB];     // 20,160 B (double-buffered)
    const int n   = blockIdx.y;
    const int tid = threadIdx.x;

    const float sxy = 15.0f / 1023.0f;
    // Row-invariant x interpolation for both pixel columns
    const int   xA  = tid,             xB  = tid + TPB;
    const float fxA = (float)xA * sxy, fxB = (float)xB * sxy;
    const int   ixA = min((int)fxA, WG - 2), ixB = min((int)fxB, WG - 2);
    const float wxA = fxA - (float)ixA,      wxB = fxB - (float)ixB;
    const float wxcA = 1.0f - wxA,           wxcB = 1.0f - wxB;

    const float* gmap  = guide + (size_t)n * HW;
    float*       obase = out   + (size_t)n * (size_t)Cc * HW;
    const uint2* gt    = g_tab + (size_t)n * 1024 * NTAB;

    int   y  = blockIdx.x;
    float gA = gmap[(size_t)y * 1024 + xA];      // guide prefetch (row y)
    float gB = gmap[(size_t)y * 1024 + xB];
    int   buf = 0;

    while (y < 1024) {
        // ---- Copy this row's table (coalesced, ~10 KB) ----
        {
            const uint2* src = gt + y * NTAB;
            uint2* dst = tabs + buf * NTAB;
            for (int s = tid; s < NTAB; s += TPB) dst[s] = __ldg(src + s);
        }
        __syncthreads();     // single barrier per row (double-buffered)

        const int ynext = y + BX;
        float gnA = 0.0f, gnB = 0.0f;
        if (ynext < 1024) {
            gnA = gmap[(size_t)ynext * 1024 + xA];
            gnB = gmap[(size_t)ynext * 1024 + xB];
        }

        // ---- Two pixels: bilinear in (x, z), fp16 quad + FFMA2 ----
        float* oprow = obase + (size_t)y * 1024;
        {
            // pixel A
            float fz  = fminf(fmaxf(gA * 7.0f, 0.0f), 7.0f);
            int   iz0 = min((int)fz, Dd - 2);
            float wz  = fz - (float)iz0, wzc = 1.0f - wz;
            uint64_t wv0 = pack2(wxcA * wzc, wxcA * wz);
            uint64_t wv1 = pack2(wxA  * wzc, wxA  * wz);
            const uint2* t = tabs + buf * NTAB + ixA * 7 + iz0;
            #pragma unroll
            for (int c = 0; c < Cc; c++) {
                uint2 q = t[c * 105];
                __half2 h0 = *reinterpret_cast<const __half2*>(&q.x);
                __half2 h1 = *reinterpret_cast<const __half2*>(&q.y);
                float2 fa = __half22float2(h0);
                float2 fb = __half22float2(h1);
                uint64_t acc = mul_f32x2(pack2(fa.x, fa.y), wv0);
                acc = fma_f32x2(pack2(fb.x, fb.y), wv1, acc);
                oprow[(size_t)c * HW + xA] = sum2(acc);
            }
        }
        {
            // pixel B
            float fz  = fminf(fmaxf(gB * 7.0f, 0.0f), 7.0f);
            int   iz0 = min((int)fz, Dd - 2);
            float wz  = fz - (float)iz0, wzc = 1.0f - wz;
            uint64_t wv0 = pack2(wxcB * wzc, wxcB * wz);
            uint64_t wv1 = pack2(wxB  * wzc, wxB  * wz);
            const uint2* t = tabs + buf * NTAB + ixB * 7 + iz0;
            #pragma unroll
            for (int c = 0; c < Cc; c++) {
                uint2 q = t[c * 105];
                __half2 h0 = *reinterpret_cast<const __half2*>(&q.x);
                __half2 h1 = *reinterpret_cast<const __half2*>(&q.y);
                float2 fa = __half22float2(h0);
                float2 fb = __half22float2(h1);
                uint64_t acc = mul_f32x2(pack2(fa.x, fa.y), wv0);
                acc = fma_f32x2(pack2(fb.x, fb.y), wv1, acc);
                oprow[(size_t)c * HW + xB] = sum2(acc);
            }
        }

        gA = gnA; gB = gnB;
        y  = ynext;
        buf ^= 1;
    }
}

extern "C" void kernel_launch(void* const* d_in, const int* in_sizes, int n_in,
                              void* d_out, int out_size)
{
    const float* grid  = (const float*)d_in[0];
    const float* guide = (const float*)d_in[1];
    float*       out   = (float*)d_out;

    cudaFuncSetAttribute(build_tables_kernel,
                         cudaFuncAttributeMaxDynamicSharedMemorySize,
                         MP_FLOATS * (int)sizeof(float));

    dim3 pre(PRE_BX, 2);
    build_tables_kernel<<<pre, PRE_TPB, MP_FLOATS * sizeof(float)>>>(grid);

    dim3 gdim(BX, 2);
    slice_operation_kernel<<<gdim, TPB>>>(guide, out);
}

// round 13
// speedup vs baseline: 1.3258x; 1.3258x over previous
#include <cuda_runtime.h>
#include <cuda_fp16.h>
#include <cstdint>

// Shapes fixed by setup_inputs():
//   grid:     (N=2, C=12, D=8, Hg=16, Wg=16) float32
//   guidemap: (N=2, 1, H=1024, W=1024)       float32
//   out:      (N=2, C=12, H=1024, W=1024)    float32
#define HW   (1024 * 1024)
#define Cc   12
#define Dd   8
#define HG   16
#define WG   16

// Padded master: mp[(c*256 + y*16 + x)*9 + z]  (z stride 1 bank -> conflict-free)
#define MP_FLOATS (Cc * 256 * 9)            // 27648 floats = 110,592 B
// Per-row fp16 quad table, entry s = (c*15 + x0)*7 + z0, uint2 = 4 x fp16:
//   .x = half2(Gy(z0,x0),   Gy(z0+1,x0))
//   .y = half2(Gy(z0,x0+1), Gy(z0+1,x0+1))
#define NTAB (Cc * 15 * 7)                  // 1260 entries, 10,080 B
#define SMEM_BYTES (MP_FLOATS * 4 + 2 * NTAB * 8)   // 130,752 B (occ = 1 blk/SM)

#define TPB 1024   // == image width: one row per block-iteration
#define BX  74     // 74 * 2 batches = 148 = one block per SM

// ---------------- packed fp32x2 helpers (FFMA2 in SASS, PTX-only) ----------
static __device__ __forceinline__ uint64_t fma_f32x2(uint64_t a, uint64_t b, uint64_t c) {
    uint64_t d; asm("fma.rn.f32x2 %0, %1, %2, %3;" : "=l"(d) : "l"(a), "l"(b), "l"(c)); return d;
}
static __device__ __forceinline__ uint64_t mul_f32x2(uint64_t a, uint64_t b) {
    uint64_t d; asm("mul.rn.f32x2 %0, %1, %2;" : "=l"(d) : "l"(a), "l"(b)); return d;
}
static __device__ __forceinline__ uint64_t pack2(float lo, float hi) {
    uint64_t d; asm("mov.b64 %0, {%1, %2};" : "=l"(d) : "f"(lo), "f"(hi)); return d;
}
static __device__ __forceinline__ float sum2(uint64_t v) {
    float lo, hi; asm("mov.b64 {%0, %1}, %2;" : "=f"(lo), "=f"(hi) : "l"(v)); return lo + hi;
}

__global__ __launch_bounds__(TPB, 1)
void slice_operation_kernel(const float* __restrict__ grid,
                            const float* __restrict__ guide,
                            float* __restrict__ out)
{
    extern __shared__ float sm[];
    uint2* tabs = (uint2*)(sm + MP_FLOATS);      // 2 x 1260 uint2 (double buffer)

    const int n   = blockIdx.y;
    const int tid = threadIdx.x;

    // ---- Stage grid[n] into z-padded master (once) ----
    const float* gsrc = grid + (size_t)n * (Cc * Dd * 256);
    for (int s = tid; s < Cc * Dd * 256; s += TPB) {
        int c   = s >> 11;
        int rem = s & 2047;
        int z   = rem >> 8;
        int pt  = rem & 255;           // y*16 + x
        sm[(c * 256 + pt) * 9 + z] = __ldg(gsrc + s);
    }
    __syncthreads();

    // ---- Build-entry decode (s = tid, and s+1024 for tid < 236) ----
    const int ca = tid / 105, ra = tid - ca * 105;
    const int xa = ra / 7,    za = ra - xa * 7;
    const int s1 = tid + TPB;
    const bool has1 = (s1 < NTAB);
    const int cb = s1 / 105,  rb = s1 - cb * 105;
    const int xb = rb / 7,    zb = rb - xb * 7;
    const int moffa = (ca * 256 + xa) * 9 + za;   // + iy0*144 at use
    const int moffb = (cb * 256 + xb) * 9 + zb;

    const float sxy = 15.0f / 1023.0f;
    // Row-invariant x interpolation (pixel column == tid)
    const float fx  = (float)tid * sxy;
    const int   ix0 = min((int)fx, WG - 2);
    const float wx  = fx - (float)ix0;
    const float wxc = 1.0f - wx;

    const float* gmap  = guide + (size_t)n * HW;
    float*       obase = out   + (size_t)n * (size_t)Cc * HW;

    int   y    = blockIdx.x;
    float gcur = gmap[(size_t)y * 1024 + tid];    // guide prefetch (row y)
    int   buf  = 0;

    while (y < 1024) {
        const float fy  = (float)y * sxy;
        const int   iy0 = min((int)fy, HG - 2);
        const float wy  = fy - (float)iy0;

        // ---- Build this row's fp16 quad table ----
        {
            const float* m = sm + moffa + iy0 * 144;
            // offsets: z+1 -> +1, x+1 -> +9, y+1 -> +144
            float a00 = m[0]  + wy * (m[144] - m[0]);    // z0 , x0
            float a10 = m[1]  + wy * (m[145] - m[1]);    // z1 , x0
            float a01 = m[9]  + wy * (m[153] - m[9]);    // z0 , x1
            float a11 = m[10] + wy * (m[154] - m[10]);   // z1 , x1
            __half2 h0 = __floats2half2_rn(a00, a10);
            __half2 h1 = __floats2half2_rn(a01, a11);
            uint2 q;
            q.x = *reinterpret_cast<const unsigned int*>(&h0);
            q.y = *reinterpret_cast<const unsigned int*>(&h1);
            tabs[buf * NTAB + tid] = q;
            if (has1) {
                const float* m2 = sm + moffb + iy0 * 144;
                float b00 = m2[0]  + wy * (m2[144] - m2[0]);
                float b10 = m2[1]  + wy * (m2[145] - m2[1]);
                float b01 = m2[9]  + wy * (m2[153] - m2[9]);
                float b11 = m2[10] + wy * (m2[154] - m2[10]);
                __half2 g0 = __floats2half2_rn(b00, b10);
                __half2 g1 = __floats2half2_rn(b01, b11);
                uint2 q2;
                q2.x = *reinterpret_cast<const unsigned int*>(&g0);
                q2.y = *reinterpret_cast<const unsigned int*>(&g1);
                tabs[buf * NTAB + s1] = q2;
            }
        }
        __syncthreads();     // one barrier per row (double-buffered)

        const int ynext = y + BX;
        float gnext = 0.0f;
        if (ynext < 1024) gnext = gmap[(size_t)ynext * 1024 + tid];  // prefetch

        // ---- Pixel (row y, column tid): bilinear in (x, z) ----
        const float fz  = fminf(fmaxf(gcur * 7.0f, 0.0f), 7.0f);
        const int   iz0 = min((int)fz, Dd - 2);
        const float wz  = fz - (float)iz0;
        const float wzc = 1.0f - wz;
        const uint64_t wv0 = pack2(wxc * wzc, wxc * wz);   // x0 weights (z0,z1)
        const uint64_t wv1 = pack2(wx  * wzc, wx  * wz);   // x1 weights (z0,z1)

        const uint2* t  = tabs + buf * NTAB + ix0 * 7 + iz0;
        float*       op = obase + (size_t)y * 1024 + tid;

        #pragma unroll
        for (int c = 0; c < Cc; c++) {
            uint2 q = t[c * 105];
            __half2 h0 = *reinterpret_cast<const __half2*>(&q.x);
            __half2 h1 = *reinterpret_cast<const __half2*>(&q.y);
            float2 fa = __half22float2(h0);
            float2 fb = __half22float2(h1);
            uint64_t acc = mul_f32x2(pack2(fa.x, fa.y), wv0);
            acc = fma_f32x2(pack2(fb.x, fb.y), wv1, acc);
            op[(size_t)c * HW] = sum2(acc);
        }

        gcur = gnext;
        y    = ynext;
        buf ^= 1;
    }
}

extern "C" void kernel_launch(void* const* d_in, const int* in_sizes, int n_in,
                              void* d_out, int out_size)
{
    const float* grid  = (const float*)d_in[0];
    const float* guide = (const float*)d_in[1];
    float*       out   = (float*)d_out;

    cudaFuncSetAttribute(slice_operation_kernel,
                         cudaFuncAttributeMaxDynamicSharedMemorySize, SMEM_BYTES);

    dim3 gdim(BX, 2);
    slice_operation_kernel<<<gdim, TPB, SMEM_BYTES>>>(grid, guide, out);
}